// round 3
// baseline (speedup 1.0000x reference)
#include <cuda_runtime.h>
#include <math_constants.h>

// contributions: [S=256, P=2000, C=200] fp32, row-major (c contiguous).
// Per (s, c) column along P: zero the top-4 (stable ties -> lower p), pass rest.
//
// R3: float4 vectorization. Each thread owns 4 adjacent c-columns and a
// P-segment (P/16 = 125 float4s): LDG.128/STG.128 cut load/store/address
// instructions 4x vs R2. 204800 threads. Per-column top-4 in registers,
// merged across 16 segments via smem with stable tie-break, then 4 zeros
// patched per column after __syncthreads().

static constexpr int S = 256;
static constexpr int P = 2000;
static constexpr int C = 200;
static constexpr int NCOL = S * C;            // 51200
static constexpr int VEC  = 4;
static constexpr int NGRP = NCOL / VEC;       // 12800 float4-column groups
static constexpr int GPS  = C / VEC;          // 50 groups per sample row
static constexpr int SEG  = 16;               // P-segments per column
static constexpr int PSEG = P / SEG;          // 125
static constexpr int U    = 5;                // 125 = 25 * 5
static constexpr int G    = 8;                // groups per block
static constexpr int BLK  = G * SEG;          // 128 threads
static constexpr int GRID = NGRP / G;         // 1600 blocks
static constexpr int CPB  = G * VEC;          // 32 columns per block

__device__ __forceinline__ void ins4(float (&t)[4], int (&ix)[4], float v, int p) {
    if (v > t[3]) {
        if (v > t[0]) {
            t[3]=t[2]; ix[3]=ix[2]; t[2]=t[1]; ix[2]=ix[1]; t[1]=t[0]; ix[1]=ix[0];
            t[0]=v; ix[0]=p;
        } else if (v > t[1]) {
            t[3]=t[2]; ix[3]=ix[2]; t[2]=t[1]; ix[2]=ix[1];
            t[1]=v; ix[1]=p;
        } else if (v > t[2]) {
            t[3]=t[2]; ix[3]=ix[2];
            t[2]=v; ix[2]=p;
        } else {
            t[3]=v; ix[3]=p;
        }
    }
}

__global__ void __launch_bounds__(BLK)
numproto_topk_zero(const float* __restrict__ in, float* __restrict__ out) {
    const int tid = threadIdx.x;
    const int seg = tid / G;                  // 0..15
    const int gi  = tid % G;                  // 0..7
    const int g   = blockIdx.x * G + gi;      // float4-group id

    const int s  = g / GPS;
    const int cg = g - s * GPS;               // float4 index within row

    const float4* ip = (const float4*)(in  + (size_t)s * P * C) + cg;
    float4*       op = (float4*)      (out + (size_t)s * P * C) + cg;
    const int rowq = C / 4;                   // 50 float4s per row

    float t[VEC][4];
    int   ix[VEC][4];
    #pragma unroll
    for (int j = 0; j < VEC; j++) {
        #pragma unroll
        for (int r = 0; r < 4; r++) { t[j][r] = -CUDART_INF_F; ix[j][r] = 0; }
    }

    const int p0 = seg * PSEG;
    for (int p = p0; p < p0 + PSEG; p += U) {
        float4 v[U];
        #pragma unroll
        for (int u = 0; u < U; u++)
            v[u] = ip[(size_t)(p + u) * rowq];
        #pragma unroll
        for (int u = 0; u < U; u++)
            op[(size_t)(p + u) * rowq] = v[u];
        #pragma unroll
        for (int u = 0; u < U; u++) {
            int pp = p + u;
            ins4(t[0], ix[0], v[u].x, pp);
            ins4(t[1], ix[1], v[u].y, pp);
            ins4(t[2], ix[2], v[u].z, pp);
            ins4(t[3], ix[3], v[u].w, pp);
        }
    }

    // exchange: [seg][rank][col] ; merge read is conflict-free
    __shared__ float sv[SEG][4][CPB];
    __shared__ int   si[SEG][4][CPB];
    #pragma unroll
    for (int j = 0; j < VEC; j++) {
        int colL = gi * VEC + j;
        #pragma unroll
        for (int r = 0; r < 4; r++) {
            sv[seg][r][colL] = t[j][r];
            si[seg][r][colL] = ix[j][r];
        }
    }

    __syncthreads();   // orders this block's copy-stores before the patch too

    if (tid < CPB) {
        const int col = blockIdx.x * CPB + tid;
        const int cs  = col / C;
        const int cc  = col - cs * C;
        float* opc = out + (size_t)cs * P * C + cc;

        float m[4] = {-CUDART_INF_F, -CUDART_INF_F, -CUDART_INF_F, -CUDART_INF_F};
        int   jx[4] = {0x7fffffff, 0x7fffffff, 0x7fffffff, 0x7fffffff};
        #pragma unroll
        for (int sg = 0; sg < SEG; sg++) {
            #pragma unroll
            for (int k = 0; k < 4; k++) {
                float v = sv[sg][k][tid];
                int   i = si[sg][k][tid];
                if (v > m[3] || (v == m[3] && i < jx[3])) {
                    if (v > m[0] || (v == m[0] && i < jx[0])) {
                        m[3]=m[2]; jx[3]=jx[2]; m[2]=m[1]; jx[2]=jx[1];
                        m[1]=m[0]; jx[1]=jx[0]; m[0]=v; jx[0]=i;
                    } else if (v > m[1] || (v == m[1] && i < jx[1])) {
                        m[3]=m[2]; jx[3]=jx[2]; m[2]=m[1]; jx[2]=jx[1];
                        m[1]=v; jx[1]=i;
                    } else if (v > m[2] || (v == m[2] && i < jx[2])) {
                        m[3]=m[2]; jx[3]=jx[2];
                        m[2]=v; jx[2]=i;
                    } else {
                        m[3]=v; jx[3]=i;
                    }
                }
            }
        }
        opc[(size_t)jx[0] * C] = 0.0f;
        opc[(size_t)jx[1] * C] = 0.0f;
        opc[(size_t)jx[2] * C] = 0.0f;
        opc[(size_t)jx[3] * C] = 0.0f;
    }
}

extern "C" void kernel_launch(void* const* d_in, const int* in_sizes, int n_in,
                              void* d_out, int out_size) {
    (void)in_sizes; (void)n_in; (void)out_size;
    const float* in  = (const float*)d_in[0];
    float*       out = (float*)d_out;
    numproto_topk_zero<<<GRID, BLK>>>(in, out);
}

// round 4
// speedup vs baseline: 1.2593x; 1.2593x over previous
#include <cuda_runtime.h>
#include <math_constants.h>

// contributions: [S=256, P=2000, C=200] fp32, row-major (c contiguous).
// Per (s, c) column along P: zero the top-4 (stable ties -> lower p), pass rest.
//
// R4: R2 structure (1 thread = 1 column-segment, 4 warps/32 columns per block,
// 204800 threads) + batched max-rejection: one fmaxf-tree + ONE branch per
// 10-element batch instead of a branch per element. Rare path does the insert.

static constexpr int S = 256;
static constexpr int P = 2000;
static constexpr int C = 200;
static constexpr int NCOL = S * C;          // 51200 columns
static constexpr int SEG  = 4;              // segments (warps) per column group
static constexpr int PSEG = P / SEG;        // 500
static constexpr int U    = 10;             // 500 = 50 * 10
static constexpr int COLS = 32;             // columns per block
static constexpr int BLK  = COLS * SEG;     // 128 threads
static constexpr int GRID = NCOL / COLS;    // 1600 blocks

__global__ void __launch_bounds__(BLK)
numproto_topk_zero(const float* __restrict__ in, float* __restrict__ out) {
    const int tid  = threadIdx.x;
    const int seg  = tid >> 5;              // 0..3
    const int lane = tid & 31;
    const int col  = blockIdx.x * COLS + lane;

    const int s = col / C;
    const int c = col - s * C;

    const float* ip = in  + (size_t)s * P * C + c;
    float*       op = out + (size_t)s * P * C + c;

    float t0 = -CUDART_INF_F, t1 = -CUDART_INF_F,
          t2 = -CUDART_INF_F, t3 = -CUDART_INF_F;
    int   i0 = 0, i1 = 0, i2 = 0, i3 = 0;

    const int p0 = seg * PSEG;
    for (int p = p0; p < p0 + PSEG; p += U) {
        float v[U];
        #pragma unroll
        for (int u = 0; u < U; u++)
            v[u] = ip[(size_t)(p + u) * C];
        #pragma unroll
        for (int u = 0; u < U; u++)
            op[(size_t)(p + u) * C] = v[u];

        // batched rejection: one branch per 10 elements
        float m01 = fmaxf(v[0], v[1]);
        float m23 = fmaxf(v[2], v[3]);
        float m45 = fmaxf(v[4], v[5]);
        float m67 = fmaxf(v[6], v[7]);
        float m89 = fmaxf(v[8], v[9]);
        float mx  = fmaxf(fmaxf(fmaxf(m01, m23), fmaxf(m45, m67)), m89);

        if (mx > t3) {  // rare after warm-up
            #pragma unroll
            for (int u = 0; u < U; u++) {
                float vv = v[u];
                if (vv > t3) {
                    int pp = p + u;
                    if (vv > t0) {
                        t3 = t2; i3 = i2; t2 = t1; i2 = i1; t1 = t0; i1 = i0;
                        t0 = vv; i0 = pp;
                    } else if (vv > t1) {
                        t3 = t2; i3 = i2; t2 = t1; i2 = i1;
                        t1 = vv; i1 = pp;
                    } else if (vv > t2) {
                        t3 = t2; i3 = i2;
                        t2 = vv; i2 = pp;
                    } else {
                        t3 = vv; i3 = pp;
                    }
                }
            }
        }
    }

    // candidate exchange: [seg][rank][col] -> conflict-free both phases
    __shared__ float sv[SEG][4][COLS];
    __shared__ int   si[SEG][4][COLS];
    sv[seg][0][lane] = t0; si[seg][0][lane] = i0;
    sv[seg][1][lane] = t1; si[seg][1][lane] = i1;
    sv[seg][2][lane] = t2; si[seg][2][lane] = i2;
    sv[seg][3][lane] = t3; si[seg][3][lane] = i3;

    __syncthreads();   // also orders this block's copy-stores before the patch

    if (tid < COLS) {
        const int pcol = blockIdx.x * COLS + tid;
        const int ps   = pcol / C;
        const int pc   = pcol - ps * C;
        float* opc = out + (size_t)ps * P * C + pc;

        float m0 = -CUDART_INF_F, m1 = -CUDART_INF_F,
              m2 = -CUDART_INF_F, m3 = -CUDART_INF_F;
        int   j0 = 0x7fffffff, j1 = 0x7fffffff,
              j2 = 0x7fffffff, j3 = 0x7fffffff;
        #pragma unroll
        for (int sg = 0; sg < SEG; sg++) {
            #pragma unroll
            for (int k = 0; k < 4; k++) {
                float v = sv[sg][k][tid];
                int   i = si[sg][k][tid];
                if (v > m3 || (v == m3 && i < j3)) {
                    if (v > m0 || (v == m0 && i < j0)) {
                        m3 = m2; j3 = j2; m2 = m1; j2 = j1; m1 = m0; j1 = j0;
                        m0 = v;  j0 = i;
                    } else if (v > m1 || (v == m1 && i < j1)) {
                        m3 = m2; j3 = j2; m2 = m1; j2 = j1;
                        m1 = v;  j1 = i;
                    } else if (v > m2 || (v == m2 && i < j2)) {
                        m3 = m2; j3 = j2;
                        m2 = v;  j2 = i;
                    } else {
                        m3 = v;  j3 = i;
                    }
                }
            }
        }
        opc[(size_t)j0 * C] = 0.0f;
        opc[(size_t)j1 * C] = 0.0f;
        opc[(size_t)j2 * C] = 0.0f;
        opc[(size_t)j3 * C] = 0.0f;
    }
}

extern "C" void kernel_launch(void* const* d_in, const int* in_sizes, int n_in,
                              void* d_out, int out_size) {
    (void)in_sizes; (void)n_in; (void)out_size;
    const float* in  = (const float*)d_in[0];
    float*       out = (float*)d_out;
    numproto_topk_zero<<<GRID, BLK>>>(in, out);
}